// round 12
// baseline (speedup 1.0000x reference)
#include <cuda_runtime.h>
#include <math.h>

#define BATCH 4
#define NPTS  8192
#define NB    256
#define XMIN  (-6.0f)
#define BW    (12.0f / 256.0f)          /* 0.046875 exact */
#define INVW  (256.0f / 12.0f)
#define EPSB  1e-4f                     /* rounding margin on slab bounds */
#define NNB   256                       /* nn blocks */

// 8 combos: c = cloud*4 + b  (cloud 0 = pred, 1 = gt)
__device__ float g_sx[8][NPTS], g_sy[8][NPTS], g_sz[8][NPTS];
__device__ int   g_boff[8][NB + 1];
__device__ float g_bsum[NNB];

__device__ __forceinline__ int bucket_of(float x) {
    int bk = (int)((x - XMIN) * INVW);
    return min(max(bk, 0), NB - 1);
}

__global__ void __launch_bounds__(1024) bucket_kernel(
    const float* __restrict__ pred, const float* __restrict__ gt)
{
    __shared__ int cnt[NB];
    __shared__ int base[NB];
    int c = blockIdx.x;                               // 0..7
    const float* src = (c < 4 ? pred : gt) + (size_t)(c & 3) * 3 * NPTS;
    int tid = threadIdx.x;

    for (int k = tid; k < NB; k += 1024) cnt[k] = 0;
    __syncthreads();

    float xr[NPTS / 1024];
    int   bkr[NPTS / 1024];
    #pragma unroll
    for (int p = 0; p < NPTS / 1024; p++) {
        int i = tid + p * 1024;
        float x = src[i];
        int bk = bucket_of(x);
        xr[p] = x;  bkr[p] = bk;
        atomicAdd(&cnt[bk], 1);
    }
    __syncthreads();

    if (tid == 0) {
        int run = 0;
        for (int k = 0; k < NB; k++) {
            base[k] = run;  g_boff[c][k] = run;  run += cnt[k];
        }
        g_boff[c][NB] = run;                          // == NPTS
    }
    __syncthreads();

    #pragma unroll
    for (int p = 0; p < NPTS / 1024; p++) {
        int i = tid + p * 1024;
        int pos = atomicAdd(&base[bkr[p]], 1);        // in-bucket order arbitrary:
        g_sx[c][pos] = xr[p];                         // min over set is order-free
        g_sy[c][pos] = src[NPTS + i];
        g_sz[c][pos] = src[2 * NPTS + i];
    }
}

__global__ void __launch_bounds__(256) nn_kernel(
    const float* __restrict__ pred, const float* __restrict__ gt)
{
    int blk = blockIdx.x;
    int qc   = blk & 31;                  // 32 query chunks of 256
    int dirb = blk >> 5;                  // 0..7
    int dir = dirb >> 2, b = dirb & 3;

    const float* Q = (dir == 0 ? pred : gt) + (size_t)b * 3 * NPTS;
    int sc = (dir == 0 ? 4 : 0) + b;      // scan the other cloud
    const float* __restrict__ SX = g_sx[sc];
    const float* __restrict__ SY = g_sy[sc];
    const float* __restrict__ SZ = g_sz[sc];
    const int*   __restrict__ BO = g_boff[sc];

    int i = qc * 256 + threadIdx.x;       // original query order -> deterministic
    float qx = Q[i], qy = Q[NPTS + i], qz = Q[2 * NPTS + i];

    int bq = bucket_of(qx);
    float best = 3.0e38f;

#define SCAN_BUCKET(KK)                                                    \
    {                                                                      \
        int e = BO[(KK) + 1];                                              \
        for (int t = BO[(KK)]; t < e; t++) {                               \
            float dx = qx - SX[t];                                         \
            float dy = qy - SY[t];                                         \
            float dz = qz - SZ[t];                                         \
            best = fminf(best, fmaf(dx, dx, fmaf(dy, dy, dz * dz)));       \
        }                                                                  \
    }

    SCAN_BUCKET(bq);
    for (int r = 1; r < NB; r++) {
        int kl = bq - r, kr = bq + r;
        // slab lower bounds on |dx| (with float-rounding margin)
        float bl = qx - (XMIN + (float)(kl + 1) * BW) - EPSB;
        float br = (XMIN + (float)kr * BW) - qx - EPSB;
        bool aL = (kl >= 0) && !(bl > 0.0f && bl * bl >= best);
        bool aR = (kr < NB) && !(br > 0.0f && br * br >= best);
        if (!aL && !aR) break;            // bounds grow with r -> safe stop
        if (aL) SCAN_BUCKET(kl);
        if (aR) SCAN_BUCKET(kr);
    }
#undef SCAN_BUCKET

    float s = sqrtf(best);                // exact min dist for this query

    __shared__ float ssum[256];
    ssum[threadIdx.x] = s;
    __syncthreads();
    for (int off = 128; off > 0; off >>= 1) {
        if (threadIdx.x < off) ssum[threadIdx.x] += ssum[threadIdx.x + off];
        __syncthreads();
    }
    if (threadIdx.x == 0) g_bsum[blk] = ssum[0];
}

__global__ void __launch_bounds__(256) final_kernel(float* __restrict__ out) {
    __shared__ float ssum[NNB];
    int tid = threadIdx.x;
    ssum[tid] = g_bsum[tid];
    __syncthreads();
    for (int off = NNB / 2; off > 0; off >>= 1) {
        if (tid < off) ssum[tid] += ssum[tid + off];
        __syncthreads();
    }
    if (tid == 0) out[0] = ssum[0] * (1.0f / (float)BATCH);
}

extern "C" void kernel_launch(void* const* d_in, const int* in_sizes, int n_in,
                              void* d_out, int out_size) {
    const float* pred = (const float*)d_in[0];
    const float* gt   = (const float*)d_in[1];
    float* out = (float*)d_out;
    (void)in_sizes; (void)n_in; (void)out_size;

    bucket_kernel<<<8, 1024>>>(pred, gt);      // x-slab CSR per (cloud, batch)
    nn_kernel<<<NNB, 256>>>(pred, gt);         // exact pruned NN, both directions
    final_kernel<<<1, NNB>>>(out);
}

// round 13
// speedup vs baseline: 1.0144x; 1.0144x over previous
#include <cuda_runtime.h>
#include <math.h>

#define BATCH 4
#define NPTS  8192
#define NB    256
#define XMIN  (-6.0f)
#define BW    (12.0f / 256.0f)          /* 0.046875 exact */
#define INVW  (256.0f / 12.0f)
#define EPSB  1e-4f                     /* margin >> ulp errors on slab edges */

// c = 0..3: pred batch c ; c = 4..7: gt batch c-4. Scan cloud of c is c^4.
__device__ float4 g_sp[8][NPTS];        // sorted points (x,y,z,-)
__device__ int    g_oi[8][NPTS];        // sorted pos -> original index
__device__ int    g_boff[8][NB + 1];    // CSR slab offsets
__device__ float  g_best[8][NPTS];      // NN distance at original index

__device__ __forceinline__ int bucket_of(float x) {
    int bk = (int)((x - XMIN) * INVW);
    return min(max(bk, 0), NB - 1);
}

__global__ void __launch_bounds__(1024) bucket_kernel(
    const float* __restrict__ pred, const float* __restrict__ gt)
{
    __shared__ int cnt[NB];
    __shared__ int base[NB];
    __shared__ int wsum[8];
    int c = blockIdx.x;                               // 0..7
    const float* src = (c < 4 ? pred : gt) + (size_t)(c & 3) * 3 * NPTS;
    int tid = threadIdx.x;
    int lane = tid & 31, w5 = tid >> 5;

    if (tid < NB) cnt[tid] = 0;
    __syncthreads();

    float xr[NPTS / 1024];
    int   bkr[NPTS / 1024];
    #pragma unroll
    for (int p = 0; p < NPTS / 1024; p++) {
        int i = tid + p * 1024;
        float x = src[i];
        int bk = bucket_of(x);
        xr[p] = x;  bkr[p] = bk;
        atomicAdd(&cnt[bk], 1);
    }
    __syncthreads();

    // parallel exclusive prefix over 256 counts (8 warps)
    int myc = 0, s = 0;
    if (tid < NB) {
        myc = cnt[tid];
        s = myc;
        #pragma unroll
        for (int o = 1; o < 32; o <<= 1) {
            int t = __shfl_up_sync(0xffffffffu, s, o);
            if (lane >= o) s += t;
        }
        if (lane == 31) wsum[w5] = s;
    }
    __syncthreads();
    if (tid < NB) {
        int woff = 0;
        #pragma unroll
        for (int k = 0; k < 8; k++) woff += (k < w5) ? wsum[k] : 0;
        int excl = woff + s - myc;
        base[tid] = excl;
        g_boff[c][tid] = excl;
    }
    if (tid == 0) g_boff[c][NB] = NPTS;
    __syncthreads();

    #pragma unroll
    for (int p = 0; p < NPTS / 1024; p++) {
        int i = tid + p * 1024;
        int pos = atomicAdd(&base[bkr[p]], 1);   // in-bucket order arbitrary:
        g_sp[c][pos] = make_float4(xr[p], src[NPTS + i], src[2 * NPTS + i], 0.0f);
        g_oi[c][pos] = i;                        // min over set is order-free
    }
}

__global__ void __launch_bounds__(256) nn_kernel() {
    int gw   = (blockIdx.x * 256 + threadIdx.x) >> 5;   // 0..2047
    int lane = threadIdx.x & 31;
    int c    = gw >> 8;                                 // 8 combos, 256 warps each
    int wq   = gw & 255;
    int sc   = c ^ 4;                                   // scan the other cloud

    const float4* __restrict__ SP = g_sp[sc];
    const int*    __restrict__ BO = g_boff[sc];

    int qpos = wq * 32 + lane;                          // sorted queries: warp
    float4 q = g_sp[c][qpos];                           // spans ~1 slab
    int oi   = g_oi[c][qpos];
    int bq   = bucket_of(q.x);
    int bmin = __reduce_min_sync(0xffffffffu, bq);      // warp-uniform window
    int bmax = __reduce_max_sync(0xffffffffu, bq);

    float best = 3.0e38f;

#define SCAN_RANGE(T0, T1)                                                 \
    for (int t = (T0); t < (T1); t++) {                                    \
        float4 sp = SP[t];                  /* lane-uniform LDG.128 */     \
        float dx = q.x - sp.x;                                             \
        float dy = q.y - sp.y;                                             \
        float dz = q.z - sp.z;                                             \
        best = fminf(best, fmaf(dx, dx, fmaf(dy, dy, dz * dz)));           \
    }

    SCAN_RANGE(BO[bmin], BO[bmax + 1]);

    for (int r = 1; r < NB; r++) {
        int kl = bmin - r, kr = bmax + r;
        float bl = q.x - (XMIN + (float)(kl + 1) * BW) - EPSB;  // lower bound
        float br = (XMIN + (float)kr * BW) - q.x - EPSB;        // on |dx|
        bool needL = (kl >= 0) && !(bl > 0.0f && bl * bl >= best);
        bool needR = (kr < NB) && !(br > 0.0f && br * br >= best);
        bool anyL = __any_sync(0xffffffffu, needL);
        bool anyR = __any_sync(0xffffffffu, needR);
        if (!anyL && !anyR) break;        // bounds grow with r -> exact stop
        if (anyL) SCAN_RANGE(BO[kl], BO[kl + 1]);
        if (anyR) SCAN_RANGE(BO[kr], BO[kr + 1]);
    }
#undef SCAN_RANGE

    g_best[c][oi] = sqrtf(best);          // original slot -> deterministic
}

__global__ void __launch_bounds__(1024) reduce_kernel(float* __restrict__ out) {
    __shared__ float ssum[1024];
    int tid = threadIdx.x;
    const float* F = &g_best[0][0];
    float s = 0.0f;
    #pragma unroll
    for (int k = tid; k < 8 * NPTS; k += 1024) s += F[k];   // fixed order
    ssum[tid] = s;
    __syncthreads();
    for (int off = 512; off > 0; off >>= 1) {
        if (tid < off) ssum[tid] += ssum[tid + off];
        __syncthreads();
    }
    if (tid == 0) out[0] = ssum[0] * (1.0f / (float)BATCH);
}

extern "C" void kernel_launch(void* const* d_in, const int* in_sizes, int n_in,
                              void* d_out, int out_size) {
    const float* pred = (const float*)d_in[0];
    const float* gt   = (const float*)d_in[1];
    float* out = (float*)d_out;
    (void)in_sizes; (void)n_in; (void)out_size;

    bucket_kernel<<<8, 1024>>>(pred, gt);     // x-slab CSR, both clouds
    nn_kernel<<<256, 256>>>();                // warp-coherent exact pruned NN
    reduce_kernel<<<1, 1024>>>(out);
}

// round 14
// speedup vs baseline: 3.4280x; 3.3791x over previous
#include <cuda_runtime.h>
#include <math.h>

#define BATCH 4
#define NPTS  8192
#define NB    256
#define XMIN  (-6.0f)
#define BW    (12.0f / 256.0f)
#define INVW  (256.0f / 12.0f)
#define EPSB  1e-4f
#define WQ    128                 /* queries per phase-A block */
#define WIN   1280                /* scan window (sorted positions) */
#define NCHW  (WIN / 256)         /* 5 chunks */
#define QBLK  (NPTS / WQ)         /* 64 blocks per combo */

// c = 0..3: pred batch c ; c = 4..7: gt batch c-4. Scan cloud of c is c^4.
__device__ float4 g_sp[8][NPTS];      // bucket-sorted points (x,y,z,-)
__device__ int    g_oi[8][NPTS];      // sorted pos -> original index
__device__ int    g_boff[8][NB + 1];  // CSR slab offsets
__device__ float  g_best[8][NPTS];    // NN distance at original index
__device__ int    g_fb_cnt;
__device__ int    g_fb_list[8 * NPTS];

__device__ __forceinline__ int bucket_of(float x) {
    int bk = (int)((x - XMIN) * INVW);
    return min(max(bk, 0), NB - 1);
}

__global__ void __launch_bounds__(1024) bucket_kernel(
    const float* __restrict__ pred, const float* __restrict__ gt)
{
    __shared__ int cnt[NB];
    __shared__ int base[NB];
    __shared__ int wsum[8];
    int c = blockIdx.x;                               // 0..7
    const float* src = (c < 4 ? pred : gt) + (size_t)(c & 3) * 3 * NPTS;
    int tid = threadIdx.x;
    int lane = tid & 31, w5 = tid >> 5;

    if (c == 0 && tid == 0) g_fb_cnt = 0;             // reset worklist

    if (tid < NB) cnt[tid] = 0;
    __syncthreads();

    float xr[NPTS / 1024];
    int   bkr[NPTS / 1024];
    #pragma unroll
    for (int p = 0; p < NPTS / 1024; p++) {
        int i = tid + p * 1024;
        float x = src[i];
        int bk = bucket_of(x);
        xr[p] = x;  bkr[p] = bk;
        atomicAdd(&cnt[bk], 1);
    }
    __syncthreads();

    int myc = 0, s = 0;                               // parallel prefix (8 warps)
    if (tid < NB) {
        myc = cnt[tid];
        s = myc;
        #pragma unroll
        for (int o = 1; o < 32; o <<= 1) {
            int t = __shfl_up_sync(0xffffffffu, s, o);
            if (lane >= o) s += t;
        }
        if (lane == 31) wsum[w5] = s;
    }
    __syncthreads();
    if (tid < NB) {
        int woff = 0;
        #pragma unroll
        for (int k = 0; k < 8; k++) woff += (k < w5) ? wsum[k] : 0;
        int excl = woff + s - myc;
        base[tid] = excl;
        g_boff[c][tid] = excl;
    }
    if (tid == 0) g_boff[c][NB] = NPTS;
    __syncthreads();

    #pragma unroll
    for (int p = 0; p < NPTS / 1024; p++) {
        int i = tid + p * 1024;
        int pos = atomicAdd(&base[bkr[p]], 1);        // in-bucket order arbitrary
        g_sp[c][pos] = make_float4(xr[p], src[NPTS + i], src[2 * NPTS + i], 0.0f);
        g_oi[c][pos] = i;
    }
}

// Phase A: fixed sorted window, R11-style tile. 512 blocks.
__global__ void __launch_bounds__(256, 4) nn_window() {
    __shared__ float4 sg[256];            // (-2gx,-2gy,-2gz,|g|^2)
    __shared__ float  rbuf[16][WQ + 1];   // row partials across v

    int blk = blockIdx.x;
    int c  = blk >> 6;                    // 8 combos
    int qb = blk & 63;
    int sc = c ^ 4;
    const float4* __restrict__ SQ = g_sp[c];
    const float4* __restrict__ SP = g_sp[sc];

    int p0 = qb * WQ;
    int ws = p0 + WQ / 2 - WIN / 2;
    ws = max(0, min(ws, NPTS - WIN));

    int tid = threadIdx.x;
    int u = tid & 15;                     // query subgroup
    int v = tid >> 4;                     // j subgroup

    float px[8], py[8], pz[8], rowmn[8];
    #pragma unroll
    for (int p = 0; p < 8; p++) {
        float4 q = SQ[p0 + p * 16 + u];
        px[p] = q.x;  py[p] = q.y;  pz[p] = q.z;
        rowmn[p] = 3.0e38f;               // tracks min(|g|^2 - 2 p.g)
    }

    for (int ch = 0; ch < NCHW; ch++) {
        __syncthreads();
        {
            float4 sp = SP[ws + ch * 256 + tid];    // coalesced
            sg[tid] = make_float4(-2.0f * sp.x, -2.0f * sp.y, -2.0f * sp.z,
                                  fmaf(sp.x, sp.x, fmaf(sp.y, sp.y, sp.z * sp.z)));
        }
        __syncthreads();

        #pragma unroll
        for (int jj = 0; jj < 16; jj++) {
            float4 g = sg[v * 16 + jj];   // 2 distinct addrs/warp -> broadcast
            #pragma unroll
            for (int p = 0; p < 8; p++) {
                float a = fmaf(pz[p], g.z, g.w);
                a = fmaf(py[p], g.y, a);
                a = fmaf(px[p], g.x, a);
                rowmn[p] = fminf(rowmn[p], a);
            }
        }
    }

    __syncthreads();
    #pragma unroll
    for (int p = 0; p < 8; p++)
        rbuf[v][p * 16 + u] = rowmn[p];   // partial over v's j-subset
    __syncthreads();

    if (tid < WQ) {                       // owner of query p0 + tid
        float m = rbuf[0][tid];
        #pragma unroll
        for (int v2 = 1; v2 < 16; v2++) m = fminf(m, rbuf[v2][tid]);

        float4 q = SQ[p0 + tid];
        float psq = fmaf(q.x, q.x, fmaf(q.y, q.y, q.z * q.z));
        float best = fmaxf(psq + m, 0.0f);

        // exactness certificate vs excluded sorted positions (bucket-sorted:
        // excluded-left x <= x[ws-1]+BW, excluded-right x >= x[ws+WIN]-BW)
        bool ok = true;
        if (ws > 0) {
            float dl = q.x - (SP[ws - 1].x + BW) - EPSB;
            ok = ok && (dl > 0.0f) && (best <= dl * dl);
        }
        if (ws + WIN < NPTS) {
            float dr = (SP[ws + WIN].x - BW) - q.x - EPSB;
            ok = ok && (dr > 0.0f) && (best <= dr * dr);
        }

        g_best[c][g_oi[c][p0 + tid]] = sqrtf(best);
        if (!ok) {
            int slot = atomicAdd(&g_fb_cnt, 1);
            g_fb_list[slot] = (c << 16) | (p0 + tid);
        }
    }
}

// Phase B: one warp per flagged query; scan CSR range |dx| <= r cooperatively.
__global__ void __launch_bounds__(256) nn_fallback() {
    int cnt = g_fb_cnt;
    int wg   = (blockIdx.x * 256 + threadIdx.x) >> 5;
    int lane = threadIdx.x & 31;
    int nw   = (gridDim.x * 256) >> 5;

    for (int w = wg; w < cnt; w += nw) {
        int pk = g_fb_list[w];
        int c = pk >> 16, qpos = pk & 0xffff;
        int sc = c ^ 4;
        const float4* __restrict__ SP = g_sp[sc];
        const int*    __restrict__ BO = g_boff[sc];

        float4 q = g_sp[c][qpos];
        int oi = g_oi[c][qpos];
        float cand = g_best[c][oi];           // phase-A upper bound (distance)
        float r = cand * 1.0001f + 1e-5f;     // fp margin

        int klo = bucket_of(q.x - r);
        int khi = bucket_of(q.x + r);
        int t0 = BO[klo], t1 = BO[khi + 1];

        float mn = 3.0e38f;                   // true NN is inside [t0,t1)
        for (int t = t0 + lane; t < t1; t += 32) {
            float4 sp = SP[t];                // coalesced across lanes
            float dx = q.x - sp.x;
            float dy = q.y - sp.y;
            float dz = q.z - sp.z;
            mn = fminf(mn, fmaf(dx, dx, fmaf(dy, dy, dz * dz)));
        }
        #pragma unroll
        for (int m = 16; m >= 1; m >>= 1)
            mn = fminf(mn, __shfl_xor_sync(0xffffffffu, mn, m));
        if (lane == 0) g_best[c][oi] = sqrtf(mn);
    }
}

__global__ void __launch_bounds__(1024) reduce_kernel(float* __restrict__ out) {
    __shared__ float ssum[1024];
    int tid = threadIdx.x;
    const float* F = &g_best[0][0];
    float s = 0.0f;
    #pragma unroll
    for (int k = tid; k < 8 * NPTS; k += 1024) s += F[k];   // fixed order
    ssum[tid] = s;
    __syncthreads();
    for (int off = 512; off > 0; off >>= 1) {
        if (tid < off) ssum[tid] += ssum[tid + off];
        __syncthreads();
    }
    if (tid == 0) out[0] = ssum[0] * (1.0f / (float)BATCH);
}

extern "C" void kernel_launch(void* const* d_in, const int* in_sizes, int n_in,
                              void* d_out, int out_size) {
    const float* pred = (const float*)d_in[0];
    const float* gt   = (const float*)d_in[1];
    float* out = (float*)d_out;
    (void)in_sizes; (void)n_in; (void)out_size;

    bucket_kernel<<<8, 1024>>>(pred, gt);   // x-slab CSR sort, both clouds
    nn_window<<<8 * QBLK, 256>>>();         // phase A: fixed sorted windows
    nn_fallback<<<128, 256>>>();            // phase B: flagged tail queries
    reduce_kernel<<<1, 1024>>>(out);
}

// round 16
// speedup vs baseline: 3.7073x; 1.0815x over previous
#include <cuda_runtime.h>
#include <math.h>

#define BATCH 4
#define NPTS  8192
#define NB    256
#define XMIN  (-6.0f)
#define BW    (12.0f / 256.0f)
#define INVW  (256.0f / 12.0f)
#define EPSB  1e-4f
#define WQ    128                 /* queries per phase-A block */
#define WIN   1024                /* scan window (sorted positions) */
#define NCHW  (WIN / 256)         /* 4 chunks */
#define QBLK  (NPTS / WQ)         /* 64 blocks per combo */

// c = 0..3: pred batch c ; c = 4..7: gt batch c-4. Scan cloud of c is c^4.
__device__ float4 g_sp[8][NPTS];      // bucket-sorted points (x,y,z,-)
__device__ int    g_oi[8][NPTS];      // sorted pos -> original index
__device__ int    g_boff[8][NB + 1];  // CSR slab offsets
__device__ int    g_cnt[8][NB];       // zero-init; re-zeroed after each use
__device__ float  g_best[8][NPTS];    // squared NN distance at original index
__device__ int    g_fb_cnt;
__device__ int    g_fb_list[8 * NPTS];

__device__ __forceinline__ int bucket_of(float x) {
    int bk = (int)((x - XMIN) * INVW);
    return min(max(bk, 0), NB - 1);
}

__device__ __forceinline__ const float* cloud_ptr(
    const float* pred, const float* gt, int c) {
    return (c < 4 ? pred : gt) + (size_t)(c & 3) * 3 * NPTS;
}

// 64 blocks: whole chip builds all 8 histograms via global atomics.
__global__ void __launch_bounds__(1024) hist_kernel(
    const float* __restrict__ pred, const float* __restrict__ gt)
{
    int t = blockIdx.x * 1024 + threadIdx.x;   // 65536 = 8 * NPTS
    int c = t >> 13, i = t & (NPTS - 1);
    const float* src = cloud_ptr(pred, gt, c);
    atomicAdd(&g_cnt[c][bucket_of(src[i])], 1);
}

// 8 blocks: per-combo prefix + scatter; zero g_cnt afterwards.
__global__ void __launch_bounds__(1024) scatter_kernel(
    const float* __restrict__ pred, const float* __restrict__ gt)
{
    __shared__ int base[NB];
    __shared__ int wsum[8];
    int c = blockIdx.x;
    const float* src = cloud_ptr(pred, gt, c);
    int tid = threadIdx.x;
    int lane = tid & 31, w5 = tid >> 5;

    if (c == 0 && tid == 0) g_fb_cnt = 0;      // reset fallback worklist

    int myc = 0, s = 0;                        // parallel exclusive prefix
    if (tid < NB) {
        myc = g_cnt[c][tid];
        s = myc;
        #pragma unroll
        for (int o = 1; o < 32; o <<= 1) {
            int t2 = __shfl_up_sync(0xffffffffu, s, o);
            if (lane >= o) s += t2;
        }
        if (lane == 31) wsum[w5] = s;
    }
    __syncthreads();
    if (tid < NB) {
        int woff = 0;
        #pragma unroll
        for (int k = 0; k < 8; k++) woff += (k < w5) ? wsum[k] : 0;
        int excl = woff + s - myc;
        base[tid] = excl;
        g_boff[c][tid] = excl;
        g_cnt[c][tid] = 0;                     // ready for next replay
    }
    if (tid == 0) g_boff[c][NB] = NPTS;
    __syncthreads();

    #pragma unroll
    for (int p = 0; p < NPTS / 1024; p++) {
        int i = tid + p * 1024;
        float x = src[i];
        int pos = atomicAdd(&base[bucket_of(x)], 1);   // in-bucket order free
        g_sp[c][pos] = make_float4(x, src[NPTS + i], src[2 * NPTS + i], 0.0f);
        g_oi[c][pos] = i;
    }
}

// Phase A: fixed sorted window, tiled. 512 blocks.
__global__ void __launch_bounds__(256, 4) nn_window() {
    __shared__ float4 sg[256];            // (-2gx,-2gy,-2gz,|g|^2)
    __shared__ float  rbuf[16][WQ + 1];

    int blk = blockIdx.x;
    int c  = blk >> 6;
    int qb = blk & 63;
    int sc = c ^ 4;
    const float4* __restrict__ SQ = g_sp[c];
    const float4* __restrict__ SP = g_sp[sc];

    int p0 = qb * WQ;
    int ws = p0 + WQ / 2 - WIN / 2;
    ws = max(0, min(ws, NPTS - WIN));

    int tid = threadIdx.x;
    int u = tid & 15;
    int v = tid >> 4;

    float px[8], py[8], pz[8], rowmn[8];
    #pragma unroll
    for (int p = 0; p < 8; p++) {
        float4 q = SQ[p0 + p * 16 + u];
        px[p] = q.x;  py[p] = q.y;  pz[p] = q.z;
        rowmn[p] = 3.0e38f;
    }

    for (int ch = 0; ch < NCHW; ch++) {
        __syncthreads();
        {
            float4 sp = SP[ws + ch * 256 + tid];
            sg[tid] = make_float4(-2.0f * sp.x, -2.0f * sp.y, -2.0f * sp.z,
                                  fmaf(sp.x, sp.x, fmaf(sp.y, sp.y, sp.z * sp.z)));
        }
        __syncthreads();

        #pragma unroll
        for (int jj = 0; jj < 16; jj++) {
            float4 g = sg[v * 16 + jj];   // 2 distinct addrs/warp -> broadcast
            #pragma unroll
            for (int p = 0; p < 8; p++) {
                float a = fmaf(pz[p], g.z, g.w);
                a = fmaf(py[p], g.y, a);
                a = fmaf(px[p], g.x, a);
                rowmn[p] = fminf(rowmn[p], a);
            }
        }
    }

    __syncthreads();
    #pragma unroll
    for (int p = 0; p < 8; p++)
        rbuf[v][p * 16 + u] = rowmn[p];
    __syncthreads();

    if (tid < WQ) {
        float m = rbuf[0][tid];
        #pragma unroll
        for (int v2 = 1; v2 < 16; v2++) m = fminf(m, rbuf[v2][tid]);

        float4 q = SQ[p0 + tid];
        float psq = fmaf(q.x, q.x, fmaf(q.y, q.y, q.z * q.z));
        float best2 = fmaxf(psq + m, 0.0f);   // exact windowed min (squared)

        // exactness certificate vs excluded sorted positions
        bool ok = true;
        if (ws > 0) {
            float dl = q.x - (SP[ws - 1].x + BW) - EPSB;
            ok = ok && (dl > 0.0f) && (best2 <= dl * dl);
        }
        if (ws + WIN < NPTS) {
            float dr = (SP[ws + WIN].x - BW) - q.x - EPSB;
            ok = ok && (dr > 0.0f) && (best2 <= dr * dr);
        }

        g_best[c][g_oi[c][p0 + tid]] = best2; // squared; sqrt in reduce
        if (!ok) {
            int slot = atomicAdd(&g_fb_cnt, 1);
            g_fb_list[slot] = (c << 16) | (p0 + tid);
        }
    }
}

// Phase B: one warp per flagged query; scan ONLY the complement of the window.
__global__ void __launch_bounds__(256) nn_fallback() {
    int cnt = g_fb_cnt;
    int wg   = (blockIdx.x * 256 + threadIdx.x) >> 5;
    int lane = threadIdx.x & 31;
    int nw   = (gridDim.x * 256) >> 5;

    for (int w = wg; w < cnt; w += nw) {
        int pk = g_fb_list[w];
        int c = pk >> 16, qpos = pk & 0xffff;
        int sc = c ^ 4;
        const float4* __restrict__ SP = g_sp[sc];
        const int*    __restrict__ BO = g_boff[sc];

        float4 q = g_sp[c][qpos];
        int oi = g_oi[c][qpos];
        float best2 = g_best[c][oi];          // exact windowed min (squared)
        float r = sqrtf(best2) * 1.0001f + 1e-5f;

        int ws = (qpos >> 7) * WQ + WQ / 2 - WIN / 2;   // same as phase A
        ws = max(0, min(ws, NPTS - WIN));

        int t0 = BO[bucket_of(q.x - r)];
        int t1 = BO[bucket_of(q.x + r) + 1];

        float mn = best2;                     // seed with window result
        int e1 = min(ws, t1);
        for (int t = t0 + lane; t < e1; t += 32) {
            float4 sp = SP[t];
            float dx = q.x - sp.x, dy = q.y - sp.y, dz = q.z - sp.z;
            mn = fminf(mn, fmaf(dx, dx, fmaf(dy, dy, dz * dz)));
        }
        int s2 = max(ws + WIN, t0);
        for (int t = s2 + lane; t < t1; t += 32) {
            float4 sp = SP[t];
            float dx = q.x - sp.x, dy = q.y - sp.y, dz = q.z - sp.z;
            mn = fminf(mn, fmaf(dx, dx, fmaf(dy, dy, dz * dz)));
        }
        #pragma unroll
        for (int m = 16; m >= 1; m >>= 1)
            mn = fminf(mn, __shfl_xor_sync(0xffffffffu, mn, m));
        if (lane == 0) g_best[c][oi] = mn;
    }
}

__global__ void __launch_bounds__(1024) reduce_kernel(float* __restrict__ out) {
    __shared__ float ssum[1024];
    int tid = threadIdx.x;
    const float4* F = (const float4*)&g_best[0][0];   // 16384 float4
    float s0 = 0.0f, s1 = 0.0f, s2 = 0.0f, s3 = 0.0f;
    #pragma unroll
    for (int k = tid; k < 16384; k += 4096) {         // 4 indep streams -> MLP
        float4 a = F[k];
        float4 b = F[k + 1024];
        float4 cc = F[k + 2048];
        float4 d = F[k + 3072];
        s0 += sqrtf(a.x) + sqrtf(a.y) + sqrtf(a.z) + sqrtf(a.w);
        s1 += sqrtf(b.x) + sqrtf(b.y) + sqrtf(b.z) + sqrtf(b.w);
        s2 += sqrtf(cc.x) + sqrtf(cc.y) + sqrtf(cc.z) + sqrtf(cc.w);
        s3 += sqrtf(d.x) + sqrtf(d.y) + sqrtf(d.z) + sqrtf(d.w);
    }
    ssum[tid] = (s0 + s1) + (s2 + s3);
    __syncthreads();
    for (int off = 512; off > 0; off >>= 1) {
        if (tid < off) ssum[tid] += ssum[tid + off];
        __syncthreads();
    }
    if (tid == 0) out[0] = ssum[0] * (1.0f / (float)BATCH);
}

extern "C" void kernel_launch(void* const* d_in, const int* in_sizes, int n_in,
                              void* d_out, int out_size) {
    const float* pred = (const float*)d_in[0];
    const float* gt   = (const float*)d_in[1];
    float* out = (float*)d_out;
    (void)in_sizes; (void)n_in; (void)out_size;

    hist_kernel<<<64, 1024>>>(pred, gt);     // full-chip histograms
    scatter_kernel<<<8, 1024>>>(pred, gt);   // prefix + scatter, zero g_cnt
    nn_window<<<8 * QBLK, 256>>>();          // phase A: fixed sorted windows
    nn_fallback<<<128, 256>>>();             // phase B: complement only
    reduce_kernel<<<1, 1024>>>(out);
}

// round 17
// speedup vs baseline: 4.8963x; 1.3207x over previous
#include <cuda_runtime.h>
#include <math.h>

#define BATCH 4
#define NPTS  8192
#define NB    256
#define XMIN  (-6.0f)
#define BW    (12.0f / 256.0f)
#define INVW  (256.0f / 12.0f)
#define EPSB  1e-4f
#define WQ    128                 /* queries per phase-A block */
#define WIN   1024                /* scan window (sorted positions) */
#define NCHW  (WIN / 256)         /* 4 chunks */
#define QBLK  (NPTS / WQ)         /* 64 blocks per combo */
#define FBLK  1024                /* fallback blocks */

// c = 0..3: pred batch c ; c = 4..7: gt batch c-4. Scan cloud of c is c^4.
__device__ float4 g_sp[8][NPTS];      // bucket-sorted points (x,y,z,-)
__device__ int    g_oi[8][NPTS];      // sorted pos -> original index
__device__ int    g_boff[8][NB + 1];  // CSR slab offsets
__device__ int    g_cnt[8][NB];       // zero-init; re-zeroed after each use
__device__ float  g_best[8][NPTS];    // squared NN distance at original index
__device__ int    g_fb_cnt;
__device__ int    g_fb_list[8 * NPTS];

__device__ __forceinline__ int bucket_of(float x) {
    int bk = (int)((x - XMIN) * INVW);
    return min(max(bk, 0), NB - 1);
}

__device__ __forceinline__ const float* cloud_ptr(
    const float* pred, const float* gt, int c) {
    return (c < 4 ? pred : gt) + (size_t)(c & 3) * 3 * NPTS;
}

// 64 blocks: whole chip builds all 8 histograms via global atomics.
__global__ void __launch_bounds__(1024) hist_kernel(
    const float* __restrict__ pred, const float* __restrict__ gt)
{
    int t = blockIdx.x * 1024 + threadIdx.x;   // 65536 = 8 * NPTS
    int c = t >> 13, i = t & (NPTS - 1);
    const float* src = cloud_ptr(pred, gt, c);
    atomicAdd(&g_cnt[c][bucket_of(src[i])], 1);
}

// 8 blocks: per-combo prefix + scatter; zero g_cnt afterwards.
__global__ void __launch_bounds__(1024) scatter_kernel(
    const float* __restrict__ pred, const float* __restrict__ gt)
{
    __shared__ int base[NB];
    __shared__ int wsum[8];
    int c = blockIdx.x;
    const float* src = cloud_ptr(pred, gt, c);
    int tid = threadIdx.x;
    int lane = tid & 31, w5 = tid >> 5;

    if (c == 0 && tid == 0) g_fb_cnt = 0;      // reset fallback worklist

    int myc = 0, s = 0;                        // parallel exclusive prefix
    if (tid < NB) {
        myc = g_cnt[c][tid];
        s = myc;
        #pragma unroll
        for (int o = 1; o < 32; o <<= 1) {
            int t2 = __shfl_up_sync(0xffffffffu, s, o);
            if (lane >= o) s += t2;
        }
        if (lane == 31) wsum[w5] = s;
    }
    __syncthreads();
    if (tid < NB) {
        int woff = 0;
        #pragma unroll
        for (int k = 0; k < 8; k++) woff += (k < w5) ? wsum[k] : 0;
        int excl = woff + s - myc;
        base[tid] = excl;
        g_boff[c][tid] = excl;
        g_cnt[c][tid] = 0;                     // ready for next replay
    }
    if (tid == 0) g_boff[c][NB] = NPTS;
    __syncthreads();

    #pragma unroll
    for (int p = 0; p < NPTS / 1024; p++) {
        int i = tid + p * 1024;
        float x = src[i];
        int pos = atomicAdd(&base[bucket_of(x)], 1);   // in-bucket order free
        g_sp[c][pos] = make_float4(x, src[NPTS + i], src[2 * NPTS + i], 0.0f);
        g_oi[c][pos] = i;
    }
}

// Phase A: fixed sorted window, tiled. 512 blocks.
__global__ void __launch_bounds__(256, 4) nn_window() {
    __shared__ float4 sg[256];            // (-2gx,-2gy,-2gz,|g|^2)
    __shared__ float  rbuf[16][WQ + 1];

    int blk = blockIdx.x;
    int c  = blk >> 6;
    int qb = blk & 63;
    int sc = c ^ 4;
    const float4* __restrict__ SQ = g_sp[c];
    const float4* __restrict__ SP = g_sp[sc];

    int p0 = qb * WQ;
    int ws = p0 + WQ / 2 - WIN / 2;
    ws = max(0, min(ws, NPTS - WIN));

    int tid = threadIdx.x;
    int u = tid & 15;
    int v = tid >> 4;

    float px[8], py[8], pz[8], rowmn[8];
    #pragma unroll
    for (int p = 0; p < 8; p++) {
        float4 q = SQ[p0 + p * 16 + u];
        px[p] = q.x;  py[p] = q.y;  pz[p] = q.z;
        rowmn[p] = 3.0e38f;
    }

    for (int ch = 0; ch < NCHW; ch++) {
        __syncthreads();
        {
            float4 sp = SP[ws + ch * 256 + tid];
            sg[tid] = make_float4(-2.0f * sp.x, -2.0f * sp.y, -2.0f * sp.z,
                                  fmaf(sp.x, sp.x, fmaf(sp.y, sp.y, sp.z * sp.z)));
        }
        __syncthreads();

        #pragma unroll
        for (int jj = 0; jj < 16; jj++) {
            float4 g = sg[v * 16 + jj];   // 2 distinct addrs/warp -> broadcast
            #pragma unroll
            for (int p = 0; p < 8; p++) {
                float a = fmaf(pz[p], g.z, g.w);
                a = fmaf(py[p], g.y, a);
                a = fmaf(px[p], g.x, a);
                rowmn[p] = fminf(rowmn[p], a);
            }
        }
    }

    __syncthreads();
    #pragma unroll
    for (int p = 0; p < 8; p++)
        rbuf[v][p * 16 + u] = rowmn[p];
    __syncthreads();

    if (tid < WQ) {
        float m = rbuf[0][tid];
        #pragma unroll
        for (int v2 = 1; v2 < 16; v2++) m = fminf(m, rbuf[v2][tid]);

        float4 q = SQ[p0 + tid];
        float psq = fmaf(q.x, q.x, fmaf(q.y, q.y, q.z * q.z));
        float best2 = fmaxf(psq + m, 0.0f);   // exact windowed min (squared)

        // exactness certificate vs excluded sorted positions
        bool ok = true;
        if (ws > 0) {
            float dl = q.x - (SP[ws - 1].x + BW) - EPSB;
            ok = ok && (dl > 0.0f) && (best2 <= dl * dl);
        }
        if (ws + WIN < NPTS) {
            float dr = (SP[ws + WIN].x - BW) - q.x - EPSB;
            ok = ok && (dr > 0.0f) && (best2 <= dr * dr);
        }

        g_best[c][g_oi[c][p0 + tid]] = best2; // squared; sqrt in reduce
        if (!ok) {
            int slot = atomicAdd(&g_fb_cnt, 1);
            g_fb_list[slot] = (c << 16) | (p0 + tid);
        }
    }
}

// Phase B: one warp per flagged query; scan ONLY the complement of the window.
// Wide grid (8192 warps) so per-warp latency chains overlap; 2-way ILP inside.
__global__ void __launch_bounds__(256) nn_fallback() {
    int cnt = g_fb_cnt;
    int wg   = (blockIdx.x * 256 + threadIdx.x) >> 5;
    int lane = threadIdx.x & 31;
    int nw   = (gridDim.x * 256) >> 5;

    for (int w = wg; w < cnt; w += nw) {
        int pk = g_fb_list[w];
        int c = pk >> 16, qpos = pk & 0xffff;
        int sc = c ^ 4;
        const float4* __restrict__ SP = g_sp[sc];
        const int*    __restrict__ BO = g_boff[sc];

        float4 q = g_sp[c][qpos];
        int oi = g_oi[c][qpos];
        float best2 = g_best[c][oi];          // exact windowed min (squared)
        float r = sqrtf(best2) * 1.0001f + 1e-5f;

        int ws = (qpos >> 7) * WQ + WQ / 2 - WIN / 2;   // same as phase A
        ws = max(0, min(ws, NPTS - WIN));

        int t0 = BO[bucket_of(q.x - r)];
        int t1 = BO[bucket_of(q.x + r) + 1];

        float mn0 = best2, mn1 = 3.0e38f;     // 2 indep accumulators -> MLP

#define SCAN_SEG(S0, S1)                                                   \
        for (int t = (S0) + lane; t < (S1); t += 64) {                     \
            float4 sp = SP[t];                                             \
            float dx = q.x - sp.x, dy = q.y - sp.y, dz = q.z - sp.z;       \
            mn0 = fminf(mn0, fmaf(dx, dx, fmaf(dy, dy, dz * dz)));         \
            int t2 = t + 32;                                               \
            if (t2 < (S1)) {                                               \
                float4 sq2 = SP[t2];                                       \
                float ex = q.x - sq2.x, ey = q.y - sq2.y, ez = q.z - sq2.z;\
                mn1 = fminf(mn1, fmaf(ex, ex, fmaf(ey, ey, ez * ez)));     \
            }                                                              \
        }

        SCAN_SEG(t0, min(ws, t1));            // left complement
        SCAN_SEG(max(ws + WIN, t0), t1);      // right complement
#undef SCAN_SEG

        float mn = fminf(mn0, mn1);
        #pragma unroll
        for (int m = 16; m >= 1; m >>= 1)
            mn = fminf(mn, __shfl_xor_sync(0xffffffffu, mn, m));
        if (lane == 0) g_best[c][oi] = mn;
    }
}

__global__ void __launch_bounds__(1024) reduce_kernel(float* __restrict__ out) {
    __shared__ float ssum[1024];
    int tid = threadIdx.x;
    const float4* F = (const float4*)&g_best[0][0];   // 16384 float4
    float s0 = 0.0f, s1 = 0.0f, s2 = 0.0f, s3 = 0.0f;
    #pragma unroll
    for (int k = tid; k < 16384; k += 4096) {         // 4 indep streams -> MLP
        float4 a = F[k];
        float4 b = F[k + 1024];
        float4 cc = F[k + 2048];
        float4 d = F[k + 3072];
        s0 += sqrtf(a.x) + sqrtf(a.y) + sqrtf(a.z) + sqrtf(a.w);
        s1 += sqrtf(b.x) + sqrtf(b.y) + sqrtf(b.z) + sqrtf(b.w);
        s2 += sqrtf(cc.x) + sqrtf(cc.y) + sqrtf(cc.z) + sqrtf(cc.w);
        s3 += sqrtf(d.x) + sqrtf(d.y) + sqrtf(d.z) + sqrtf(d.w);
    }
    ssum[tid] = (s0 + s1) + (s2 + s3);
    __syncthreads();
    for (int off = 512; off > 0; off >>= 1) {
        if (tid < off) ssum[tid] += ssum[tid + off];
        __syncthreads();
    }
    if (tid == 0) out[0] = ssum[0] * (1.0f / (float)BATCH);
}

extern "C" void kernel_launch(void* const* d_in, const int* in_sizes, int n_in,
                              void* d_out, int out_size) {
    const float* pred = (const float*)d_in[0];
    const float* gt   = (const float*)d_in[1];
    float* out = (float*)d_out;
    (void)in_sizes; (void)n_in; (void)out_size;

    hist_kernel<<<64, 1024>>>(pred, gt);     // full-chip histograms
    scatter_kernel<<<8, 1024>>>(pred, gt);   // prefix + scatter, zero g_cnt
    nn_window<<<8 * QBLK, 256>>>();          // phase A: fixed sorted windows
    nn_fallback<<<FBLK, 256>>>();            // phase B: wide grid, complement only
    reduce_kernel<<<1, 1024>>>(out);
}